// round 15
// baseline (speedup 1.0000x reference)
#include <cuda_runtime.h>
#include <cuda_fp16.h>
#include <math.h>
#include <stdint.h>

#define Bdim 2
#define Tdim 4096
#define Cdim 2048
#define HSZ  64
#define Mrows 8192
static const size_t BTC = (size_t)Mrows * Cdim;

// ---------------- scratch ----------------
__device__ __half g_xr[(size_t)Mrows * Cdim];
__device__ __half g_xw[(size_t)Mrows * Cdim];
__device__ __half g_xk[(size_t)Mrows * Cdim];
__device__ __half g_xv[(size_t)Mrows * Cdim];
__device__ __half g_xa[(size_t)Mrows * Cdim];
__device__ __half g_xg[(size_t)Mrows * Cdim];
__device__ __half g_wr[(size_t)Cdim * Cdim];
__device__ __half g_wk[(size_t)Cdim * Cdim];
__device__ __half g_wv[(size_t)Cdim * Cdim];
__device__ __half g_w1p[(size_t)128 * Cdim];
__device__ __half g_a1p[(size_t)128 * Cdim];
__device__ __half g_v1p[(size_t)128 * Cdim];
__device__ __half g_g1p[(size_t)256 * Cdim];
__device__ __half g_w2p[(size_t)Cdim * 128];
__device__ __half g_a2p[(size_t)Cdim * 128];
__device__ __half g_v2p[(size_t)Cdim * 128];
__device__ __half g_g2p[(size_t)Cdim * 256];
__device__ __half g_hw[(size_t)Mrows * 128];
__device__ __half g_ha[(size_t)Mrows * 128];
__device__ __half g_hv[(size_t)Mrows * 128];
__device__ __half g_hg[(size_t)Mrows * 256];
__device__ float  g_ko[(size_t)Mrows * Cdim];
__device__ float  g_vg[(size_t)Mrows * Cdim];

// ---------------- helpers ----------------
__device__ __forceinline__ float sigmoidf_(float y) { return 1.0f / (1.0f + expf(-y)); }

__device__ __forceinline__ uint32_t smem_u32(const void* p) {
    uint32_t a;
    asm("{ .reg .u64 t; cvta.to.shared.u64 t, %1; cvt.u32.u64 %0, t; }" : "=r"(a) : "l"(p));
    return a;
}
__device__ __forceinline__ void mma16(float* d, const uint32_t* a, const uint32_t* b) {
    asm volatile("mma.sync.aligned.m16n8k16.row.col.f32.f16.f16.f32 "
        "{%0,%1,%2,%3}, {%4,%5,%6,%7}, {%8,%9}, {%0,%1,%2,%3};"
        : "+f"(d[0]), "+f"(d[1]), "+f"(d[2]), "+f"(d[3])
        : "r"(a[0]), "r"(a[1]), "r"(a[2]), "r"(a[3]), "r"(b[0]), "r"(b[1]));
}
__device__ __forceinline__ void cpa16(uint32_t dst, const __half* src) {
    asm volatile("cp.async.cg.shared.global [%0], [%1], 16;"
        :: "r"(dst), "l"(__cvta_generic_to_global(src)));
}
#define CP_COMMIT() asm volatile("cp.async.commit_group;" ::: "memory")
#define CP_WAIT2()  asm volatile("cp.async.wait_group 2;" ::: "memory")
#define LDSM4(r0,r1,r2,r3,addr) \
    asm volatile("ldmatrix.sync.aligned.m8n8.x4.shared.b16 {%0,%1,%2,%3}, [%4];" \
        : "=r"(r0), "=r"(r1), "=r"(r2), "=r"(r3) : "r"(addr))

__device__ __forceinline__ void stcs2(float* p, float a, float b) {
    asm volatile("st.global.cs.v2.f32 [%0], {%1, %2};" :: "l"(p), "f"(a), "f"(b) : "memory");
}
__device__ __forceinline__ void stcs_u32(void* p, uint32_t v) {
    asm volatile("st.global.cs.b32 [%0], %1;" :: "l"(p), "r"(v) : "memory");
}
__device__ __forceinline__ float2 ldcs2(const float* p) {
    float2 v;
    asm volatile("ld.global.cs.v2.f32 {%0, %1}, [%2];" : "=f"(v.x), "=f"(v.y) : "l"(p));
    return v;
}

// stage size: 128 rows x 32 halves = 8192 bytes per operand; 4 stages
#define STGB 8192
#define NSTG 4

// ---------------- mainloop: 128x128 tile, KC=32, 4-stage cp.async, ldmatrix ----
__device__ __forceinline__ void mainloop(
    const __half* __restrict__ A, const __half* __restrict__ Bm,
    int K, int m0, int n0, uint32_t sA, uint32_t sB, float acc[4][4][4])
{
    const int tid  = threadIdx.x;
    const int lane = tid & 31;
    const int wid  = tid >> 5;
    const int wm   = (wid >> 2) * 64;
    const int wn   = (wid & 3) * 32;

    const int rA  = tid >> 2;
    const int cA  = tid & 3;
    const int rA2 = rA + 64;
    const uint32_t o0 = rA  * 64 + ((cA ^ ((rA  >> 1) & 3)) * 16);
    const uint32_t o1 = rA2 * 64 + ((cA ^ ((rA2 >> 1) & 3)) * 16);
    const __half* Ag0 = A  + (size_t)(m0 + rA)  * K + cA * 8;
    const __half* Ag1 = A  + (size_t)(m0 + rA2) * K + cA * 8;
    const __half* Bg0 = Bm + (size_t)(n0 + rA)  * K + cA * 8;
    const __half* Bg1 = Bm + (size_t)(n0 + rA2) * K + cA * 8;

    const int rowadd = (lane & 7) + ((lane >> 3) & 1) * 8;
    const int swz    = (rowadd >> 1) & 3;
    const int cbit   = lane >> 4;

    const int NIT = K >> 5;
    #pragma unroll
    for (int s = 0; s < 3; s++) {
        const int k0 = s << 5;
        cpa16(sA + s * STGB + o0, Ag0 + k0);
        cpa16(sA + s * STGB + o1, Ag1 + k0);
        cpa16(sB + s * STGB + o0, Bg0 + k0);
        cpa16(sB + s * STGB + o1, Bg1 + k0);
        CP_COMMIT();
    }
    CP_WAIT2();
    __syncthreads();

    int s = 0;
    for (int it = 0; it < NIT; it++) {
        const uint32_t bA = sA + s * STGB;
        const uint32_t bB = sB + s * STGB;
        #pragma unroll
        for (int kb = 0; kb < 2; kb++) {
            const uint32_t choff = (uint32_t)((((kb << 1) + cbit) ^ swz) * 16);
            const uint32_t aaddr = bA + (wm + rowadd) * 64 + choff;
            const uint32_t baddr = bB + (wn + rowadd) * 64 + choff;
            uint32_t af[4][4], br[2][4];
            #pragma unroll
            for (int mf = 0; mf < 4; mf++)
                LDSM4(af[mf][0], af[mf][1], af[mf][2], af[mf][3], aaddr + mf * 1024);
            #pragma unroll
            for (int nb = 0; nb < 2; nb++)
                LDSM4(br[nb][0], br[nb][1], br[nb][2], br[nb][3], baddr + nb * 1024);
            #pragma unroll
            for (int mf = 0; mf < 4; mf++) {
                #pragma unroll
                for (int nf = 0; nf < 4; nf++) {
                    uint32_t b2[2] = { br[nf >> 1][nf & 1], br[nf >> 1][(nf & 1) + 2] };
                    mma16(acc[mf][nf], af[mf], b2);
                }
            }
        }
        if (it + 3 < NIT) {
            int s2 = s + 3; if (s2 >= NSTG) s2 -= NSTG;
            const int k0 = (it + 3) << 5;
            cpa16(sA + s2 * STGB + o0, Ag0 + k0);
            cpa16(sA + s2 * STGB + o1, Ag1 + k0);
            cpa16(sB + s2 * STGB + o0, Bg0 + k0);
            cpa16(sB + s2 * STGB + o1, Bg1 + k0);
        }
        CP_COMMIT();
        CP_WAIT2();
        __syncthreads();
        if (++s == NSTG) s = 0;
    }
}

#define EPI_NONE 0
#define EPI_TANH 1
#define EPI_SIG  3

__device__ __forceinline__ void zero_acc(float acc[4][4][4]) {
    #pragma unroll
    for (int i = 0; i < 4; i++)
        #pragma unroll
        for (int j = 0; j < 4; j++)
            #pragma unroll
            for (int q = 0; q < 4; q++) acc[i][j][q] = 0.0f;
}

// ---------------- merged K=2048 GEMMs: big-3 (3072 CTAs) + LoRA s1 (320) ------
__global__ __launch_bounds__(256, 2) void gemm_k2048(float* __restrict__ out_r)
{
    __shared__ __half smA[NSTG * STGB / 2];
    __shared__ __half smB[NSTG * STGB / 2];
    const int bid = blockIdx.x;

    const __half* A;
    const __half* Wp;
    float* Of = nullptr;
    __half* Oh = nullptr;
    int m0, n0 = 0, Nst = 2048, epi = EPI_NONE;

    if (bid < 3072) {
        const int g = bid >> 10, rem = bid & 1023;
        m0 = (rem >> 4) * 128;
        n0 = (rem & 15) * 128;
        A  = (g == 0) ? g_xr : (g == 1) ? g_xk : g_xv;
        Wp = (g == 0) ? g_wr : (g == 1) ? g_wk : g_wv;
        Of = (g == 0) ? out_r : (g == 1) ? g_ko : g_vg;
    } else {
        const int sid = bid - 3072;
        const int job = sid >> 6;                 // 0..4
        m0 = (sid & 63) * 128;
        if (job == 0)      { A = g_xw; Wp = g_w1p; Oh = g_hw; Nst = 128; epi = EPI_TANH; }
        else if (job == 1) { A = g_xa; Wp = g_a1p; Oh = g_ha; Nst = 128; }
        else if (job == 2) { A = g_xv; Wp = g_v1p; Oh = g_hv; Nst = 128; }
        else               { A = g_xg; Wp = g_g1p; Oh = g_hg; Nst = 256; epi = EPI_SIG;
                             n0 = (job == 4) ? 128 : 0; }
    }

    float acc[4][4][4];
    zero_acc(acc);
    mainloop(A, Wp, Cdim, m0, n0, smem_u32(smA), smem_u32(smB), acc);

    const int lane = threadIdx.x & 31;
    const int wid  = threadIdx.x >> 5;
    const int wm = (wid >> 2) * 64, wn = (wid & 3) * 32;
    const int tq = lane >> 2, tr = lane & 3;

    if (Of) {
        #pragma unroll
        for (int mf = 0; mf < 4; mf++) {
            #pragma unroll
            for (int nf = 0; nf < 4; nf++) {
                const int n = n0 + wn + nf * 8 + tr * 2;
                #pragma unroll
                for (int h = 0; h < 2; h++) {
                    const int m = m0 + wm + mf * 16 + tq + h * 8;
                    stcs2(&Of[(size_t)m * 2048 + n],
                          acc[mf][nf][h * 2], acc[mf][nf][h * 2 + 1]);
                }
            }
        }
    } else {
        #pragma unroll
        for (int mf = 0; mf < 4; mf++) {
            #pragma unroll
            for (int nf = 0; nf < 4; nf++) {
                const int n = n0 + wn + nf * 8 + tr * 2;
                #pragma unroll
                for (int h = 0; h < 2; h++) {
                    const int m = m0 + wm + mf * 16 + tq + h * 8;
                    float o0 = acc[mf][nf][h * 2], o1 = acc[mf][nf][h * 2 + 1];
                    if (epi == EPI_TANH)     { o0 = tanhf(o0); o1 = tanhf(o1); }
                    else if (epi == EPI_SIG) { o0 = sigmoidf_(o0); o1 = sigmoidf_(o1); }
                    __half2 hv = __floats2half2_rn(o0, o1);
                    *(__half2*)&Oh[(size_t)m * Nst + n] = hv;
                }
            }
        }
    }
}

// ---------------- LoRA stage-2 (z-merged; z==1 fuses a + k_final + kk) --------
__global__ __launch_bounds__(256, 2) void gemm_s2(
    float* __restrict__ out_w, float* __restrict__ out_a,
    float* __restrict__ out_v, float* __restrict__ out_g,
    float* __restrict__ out_k, float* __restrict__ out_kk,
    const float* __restrict__ w0, const float* __restrict__ a0,
    const float* __restrict__ v0, const float* __restrict__ vfp,
    const float* __restrict__ k_k, const float* __restrict__ k_a)
{
    __shared__ __half smA[NSTG * STGB / 2];
    __shared__ __half smB[NSTG * STGB / 2];
    __shared__ float smRed[8][64];
    const int z = blockIdx.z;
    const __half* A;
    const __half* Wp;
    float* O;
    const float* bias = nullptr;
    int K, epi;  // epi: 0=W, 1=fused-a, 2=vmix, 3=none
    if (z == 0)      { A = g_hw; Wp = g_w2p; O = out_w; K = 128; epi = 0; bias = w0; }
    else if (z == 1) { A = g_ha; Wp = g_a2p; O = out_a; K = 128; epi = 1; bias = a0; }
    else if (z == 2) { A = g_hv; Wp = g_v2p; O = out_v; K = 128; epi = 2; bias = v0; }
    else             { A = g_hg; Wp = g_g2p; O = out_g; K = 256; epi = 3; }

    const int n0 = blockIdx.x * 128;
    const int m0 = blockIdx.y * 128;
    float acc[4][4][4];
    zero_acc(acc);
    mainloop(A, Wp, K, m0, n0, smem_u32(smA), smem_u32(smB), acc);

    const int lane = threadIdx.x & 31;
    const int wid  = threadIdx.x >> 5;
    const int wm = (wid >> 2) * 64, wn = (wid & 3) * 32;
    const int tq = lane >> 2, tr = lane & 3;

    if (epi == 1) {
        // fused: a = sigmoid(a0+acc); k_final = ko*(1+(a-1)*k_a); kk = normalize(ko*k_k)
        float ss[4][2] = {};
        #pragma unroll
        for (int mf = 0; mf < 4; mf++) {
            #pragma unroll
            for (int nf = 0; nf < 4; nf++) {
                const int n = n0 + wn + nf * 8 + tr * 2;
                const float bv0 = bias[n], bv1 = bias[n + 1];
                const float kc0 = k_k[n], kc1 = k_k[n + 1];
                const float ka0 = k_a[n], ka1 = k_a[n + 1];
                #pragma unroll
                for (int h = 0; h < 2; h++) {
                    const int m = m0 + wm + mf * 16 + tq + h * 8;
                    const size_t ix = (size_t)m * Cdim + n;
                    float a0v = sigmoidf_(acc[mf][nf][h * 2]     + bv0);
                    float a1v = sigmoidf_(acc[mf][nf][h * 2 + 1] + bv1);
                    stcs2(&out_a[ix], a0v, a1v);
                    float2 kr = *(const float2*)&g_ko[ix];
                    stcs2(&out_k[ix],
                          kr.x * fmaf(a0v - 1.0f, ka0, 1.0f),
                          kr.y * fmaf(a1v - 1.0f, ka1, 1.0f));
                    float kk0 = kr.x * kc0, kk1 = kr.y * kc1;
                    ss[mf][h] += kk0 * kk0 + kk1 * kk1;
                }
            }
        }
        #pragma unroll
        for (int mf = 0; mf < 4; mf++)
            #pragma unroll
            for (int h = 0; h < 2; h++) {
                ss[mf][h] += __shfl_xor_sync(0xFFFFFFFFu, ss[mf][h], 1);
                ss[mf][h] += __shfl_xor_sync(0xFFFFFFFFu, ss[mf][h], 2);
            }
        if (tr == 0) {
            #pragma unroll
            for (int mf = 0; mf < 4; mf++)
                #pragma unroll
                for (int h = 0; h < 2; h++)
                    smRed[wid][mf * 16 + h * 8 + tq] = ss[mf][h];
        }
        __syncthreads();
        float inv[4][2];
        #pragma unroll
        for (int mf = 0; mf < 4; mf++)
            #pragma unroll
            for (int h = 0; h < 2; h++) {
                const int ml = mf * 16 + h * 8 + tq;
                float t = smRed[wid][ml] + smRed[wid ^ 1][ml];
                inv[mf][h] = 1.0f / fmaxf(sqrtf(t), 1e-12f);
            }
        #pragma unroll
        for (int mf = 0; mf < 4; mf++) {
            #pragma unroll
            for (int nf = 0; nf < 4; nf++) {
                const int n = n0 + wn + nf * 8 + tr * 2;
                const float kc0 = k_k[n], kc1 = k_k[n + 1];
                #pragma unroll
                for (int h = 0; h < 2; h++) {
                    const int m = m0 + wm + mf * 16 + tq + h * 8;
                    const size_t ix = (size_t)m * Cdim + n;
                    float2 kr = *(const float2*)&g_ko[ix];
                    stcs2(&out_kk[ix], kr.x * kc0 * inv[mf][h], kr.y * kc1 * inv[mf][h]);
                }
            }
        }
        return;
    }

    #pragma unroll
    for (int mf = 0; mf < 4; mf++) {
        #pragma unroll
        for (int nf = 0; nf < 4; nf++) {
            const int n = n0 + wn + nf * 8 + tr * 2;
            float bv0 = 0.0f, bv1 = 0.0f;
            if (bias) { bv0 = bias[n]; bv1 = bias[n + 1]; }
            #pragma unroll
            for (int h = 0; h < 2; h++) {
                const int m = m0 + wm + mf * 16 + tq + h * 8;
                float v0c = acc[mf][nf][h * 2], v1c = acc[mf][nf][h * 2 + 1];
                float o0, o1;
                if (epi == 0) {
                    float y0 = bv0 + v0c, y1 = bv1 + v1c;
                    o0 = -(fmaxf(-y0, 0.0f) + log1pf(expf(-fabsf(y0)))) - 0.5f;
                    o1 = -(fmaxf(-y1, 0.0f) + log1pf(expf(-fabsf(y1)))) - 0.5f;
                } else if (epi == 2) {
                    float s0 = sigmoidf_(bv0 + v0c), s1 = sigmoidf_(bv1 + v1c);
                    size_t ix = (size_t)m * Cdim + n;
                    float2 vg2 = ldcs2(&g_vg[ix]);
                    float2 vfv = ldcs2(&vfp[ix]);
                    o0 = vg2.x + (vfv.x - vg2.x) * s0;
                    o1 = vg2.y + (vfv.y - vg2.y) * s1;
                } else { o0 = v0c; o1 = v1c; }
                stcs2(&O[(size_t)m * Cdim + n], o0, o1);
            }
        }
    }
}

// ---------------- merged prologue: mix + prep_big + prep_l1t + prep_l2t -------
// bid ranges: [0,16384) mix | [16384,28672) prep_big | [28672,30720) l1t | [30720,32768) l2t
__global__ __launch_bounds__(256) void prologue(
    const float* __restrict__ x, const float* __restrict__ vf,
    const float* __restrict__ mr, const float* __restrict__ mw,
    const float* __restrict__ mk, const float* __restrict__ mv,
    const float* __restrict__ ma, const float* __restrict__ mg,
    float* __restrict__ out_vf,
    const float* __restrict__ Wr, const float* __restrict__ Wk, const float* __restrict__ Wv,
    const float* __restrict__ w1, const float* __restrict__ a1,
    const float* __restrict__ v1, const float* __restrict__ g1,
    const float* __restrict__ w2, const float* __restrict__ a2,
    const float* __restrict__ v2, const float* __restrict__ g2)
{
    __shared__ float sm[32][33];
    const int bid = blockIdx.x;
    const int tid = threadIdx.x;

    if (bid < 16384) {
        // ---- mix ----
        size_t idx = ((size_t)bid * 256 + tid) * 4;
        int c   = (int)(idx & (Cdim - 1));
        int row = (int)(idx >> 11);
        int t   = row & (Tdim - 1);
        float4 xc = *(const float4*)&x[idx];
        float4 xp = (t == 0) ? make_float4(0.f, 0.f, 0.f, 0.f) : *(const float4*)&x[idx - Cdim];
        float4 xx = make_float4(xp.x - xc.x, xp.y - xc.y, xp.z - xc.z, xp.w - xc.w);
        float4 vfv = *(const float4*)&vf[idx];
        stcs2(&out_vf[idx],     vfv.x, vfv.y);
        stcs2(&out_vf[idx + 2], vfv.z, vfv.w);
        #define DOMIX(dst, mm) do { \
            float4 mv_ = *(const float4*)&mm[c]; \
            __half2 h0_ = __floats2half2_rn(fmaf(xx.x, mv_.x, xc.x), fmaf(xx.y, mv_.y, xc.y)); \
            __half2 h1_ = __floats2half2_rn(fmaf(xx.z, mv_.z, xc.z), fmaf(xx.w, mv_.w, xc.w)); \
            uint2 u_; u_.x = *(uint32_t*)&h0_; u_.y = *(uint32_t*)&h1_; \
            *(uint2*)&dst[idx] = u_; \
        } while (0)
        DOMIX(g_xr, mr); DOMIX(g_xw, mw); DOMIX(g_xk, mk);
        DOMIX(g_xv, mv); DOMIX(g_xa, ma); DOMIX(g_xg, mg);
        #undef DOMIX
    } else if (bid < 28672) {
        // ---- prep_big ----
        const int pb = bid - 16384;
        const int z = pb >> 12;                  // 0..2
        size_t idx = ((size_t)(pb & 4095) * 256 + tid) * 4;
        const float* W = (z == 0) ? Wr : (z == 1) ? Wk : Wv;
        __half* P = (z == 0) ? g_wr : (z == 1) ? g_wk : g_wv;
        float4 wv = *(const float4*)&W[idx];
        __half2 h0 = __floats2half2_rn(wv.x, wv.y);
        __half2 h1 = __floats2half2_rn(wv.z, wv.w);
        uint2 u; u.x = *(uint32_t*)&h0; u.y = *(uint32_t*)&h1;
        *(uint2*)&P[idx] = u;
    } else if (bid < 30720) {
        // ---- prep_l1t: src [C, D_] -> dst [Dp, C] ----
        const int sid = bid - 28672;
        const int z = sid >> 9;                   // 0..3
        const int r = sid & 511;
        const int by = r >> 6, bx = r & 63;       // y in [0,8), x in [0,64)
        const float* src = (z == 0) ? w1 : (z == 1) ? a1 : (z == 2) ? v1 : g1;
        __half* dst = (z == 0) ? g_w1p : (z == 1) ? g_a1p : (z == 2) ? g_v1p : g_g1p;
        const int D_ = (z == 0) ? 128 : (z == 1) ? 128 : (z == 2) ? 64 : 224;
        const int Dp = (z == 3) ? 256 : 128;
        const int nn_t = by * 32;
        if (nn_t < Dp) {
            const int k_t = bx * 32;
            const int tx = tid & 31, ty = tid >> 5;
            #pragma unroll
            for (int i = 0; i < 4; i++) {
                const int k = k_t + ty + i * 8;
                const int nn = nn_t + tx;
                sm[ty + i * 8][tx] = (nn < D_) ? src[(size_t)k * D_ + nn] : 0.0f;
            }
            __syncthreads();
            #pragma unroll
            for (int i = 0; i < 4; i++) {
                const int nn = nn_t + ty + i * 8;
                const int k = k_t + tx;
                dst[(size_t)nn * Cdim + k] = __float2half(sm[tx][ty + i * 8]);
            }
        }
    } else {
        // ---- prep_l2t: src [D_, C] -> dst [C, Dp] ----
        const int sid = bid - 30720;
        const int z = sid >> 9;
        const int r = sid & 511;
        const int by = r >> 6, bx = r & 63;
        const float* src = (z == 0) ? w2 : (z == 1) ? a2 : (z == 2) ? v2 : g2;
        __half* dst = (z == 0) ? g_w2p : (z == 1) ? g_a2p : (z == 2) ? g_v2p : g_g2p;
        const int D_ = (z == 0) ? 128 : (z == 1) ? 128 : (z == 2) ? 64 : 224;
        const int Dp = (z == 3) ? 256 : 128;
        const int d_t = by * 32;
        if (d_t < Dp) {
            const int nn_t = bx * 32;
            const int tx = tid & 31, ty = tid >> 5;
            #pragma unroll
            for (int i = 0; i < 4; i++) {
                const int d = d_t + ty + i * 8;
                const int nn = nn_t + tx;
                sm[ty + i * 8][tx] = (d < D_) ? src[(size_t)d * Cdim + nn] : 0.0f;
            }
            __syncthreads();
            #pragma unroll
            for (int i = 0; i < 4; i++) {
                const int nn = nn_t + ty + i * 8;
                const int d = d_t + tx;
                dst[(size_t)nn * Dp + d] = __float2half(sm[tx][ty + i * 8]);
            }
        }
    }
}

// ---------------- launch ----------------
extern "C" void kernel_launch(void* const* d_in, const int* in_sizes, int n_in,
                              void* d_out, int out_size)
{
    const float* x   = (const float*)d_in[0];
    const float* vf  = (const float*)d_in[1];
    const float* x_r = (const float*)d_in[2];
    const float* x_w = (const float*)d_in[3];
    const float* x_k = (const float*)d_in[4];
    const float* x_v = (const float*)d_in[5];
    const float* x_a = (const float*)d_in[6];
    const float* x_g = (const float*)d_in[7];
    const float* w0  = (const float*)d_in[8];
    const float* w1  = (const float*)d_in[9];
    const float* w2  = (const float*)d_in[10];
    const float* a0  = (const float*)d_in[11];
    const float* a1  = (const float*)d_in[12];
    const float* a2  = (const float*)d_in[13];
    const float* v0  = (const float*)d_in[14];
    const float* v1  = (const float*)d_in[15];
    const float* v2  = (const float*)d_in[16];
    const float* g1  = (const float*)d_in[17];
    const float* g2  = (const float*)d_in[18];
    const float* k_k = (const float*)d_in[19];
    const float* k_a = (const float*)d_in[20];
    const float* Wr  = (const float*)d_in[21];
    const float* Wk  = (const float*)d_in[22];
    const float* Wv  = (const float*)d_in[23];
    (void)in_sizes; (void)n_in; (void)out_size;

    float* out = (float*)d_out;
    float* out_r  = out + 0 * BTC;
    float* out_w  = out + 1 * BTC;
    float* out_k  = out + 2 * BTC;
    float* out_v  = out + 3 * BTC;
    float* out_a  = out + 4 * BTC;
    float* out_g  = out + 5 * BTC;
    float* out_kk = out + 6 * BTC;
    float* out_vf = out + 7 * BTC;

    // 1. merged prologue (mix + all weight preps) in one flat launch
    prologue<<<32768, 256>>>(x, vf, x_r, x_w, x_k, x_v, x_a, x_g, out_vf,
                             Wr, Wk, Wv, w1, a1, v1, g1, w2, a2, v2, g2);

    // 2. all K=2048 GEMMs in one flat launch (big-3 first, s1 in the tail wave)
    gemm_k2048<<<3392, 256>>>(out_r);

    // 3. LoRA stage 2 (merged, fused epilogues; z==1 also emits k_final + kk)
    gemm_s2<<<dim3(Cdim / 128, Mrows / 128, 4), 256>>>(
        out_w, out_a, out_v, out_g, out_k, out_kk, w0, a0, v0, vf, k_k, k_a);
}

// round 16
// speedup vs baseline: 1.0275x; 1.0275x over previous
#include <cuda_runtime.h>
#include <cuda_fp16.h>
#include <math.h>
#include <stdint.h>

#define Bdim 2
#define Tdim 4096
#define Cdim 2048
#define HSZ  64
#define Mrows 8192
static const size_t BTC = (size_t)Mrows * Cdim;

// ---------------- scratch ----------------
__device__ __half g_xr[(size_t)Mrows * Cdim];
__device__ __half g_xw[(size_t)Mrows * Cdim];
__device__ __half g_xk[(size_t)Mrows * Cdim];
__device__ __half g_xv[(size_t)Mrows * Cdim];
__device__ __half g_xa[(size_t)Mrows * Cdim];
__device__ __half g_xg[(size_t)Mrows * Cdim];
__device__ __half g_wr[(size_t)Cdim * Cdim];
__device__ __half g_wk[(size_t)Cdim * Cdim];
__device__ __half g_wv[(size_t)Cdim * Cdim];
__device__ __half g_w1p[(size_t)128 * Cdim];
__device__ __half g_a1p[(size_t)128 * Cdim];
__device__ __half g_v1p[(size_t)128 * Cdim];
__device__ __half g_g1p[(size_t)256 * Cdim];
__device__ __half g_w2p[(size_t)Cdim * 128];
__device__ __half g_a2p[(size_t)Cdim * 128];
__device__ __half g_v2p[(size_t)Cdim * 128];
__device__ __half g_g2p[(size_t)Cdim * 256];
__device__ __half g_hw[(size_t)Mrows * 128];
__device__ __half g_ha[(size_t)Mrows * 128];
__device__ __half g_hv[(size_t)Mrows * 128];
__device__ __half g_hg[(size_t)Mrows * 256];
__device__ float  g_ko[(size_t)Mrows * Cdim];
__device__ float  g_vg[(size_t)Mrows * Cdim];

// ---------------- helpers ----------------
__device__ __forceinline__ float sigmoidf_(float y) { return 1.0f / (1.0f + expf(-y)); }

__device__ __forceinline__ uint32_t smem_u32(const void* p) {
    uint32_t a;
    asm("{ .reg .u64 t; cvta.to.shared.u64 t, %1; cvt.u32.u64 %0, t; }" : "=r"(a) : "l"(p));
    return a;
}
__device__ __forceinline__ void mma16(float* d, const uint32_t* a, const uint32_t* b) {
    asm volatile("mma.sync.aligned.m16n8k16.row.col.f32.f16.f16.f32 "
        "{%0,%1,%2,%3}, {%4,%5,%6,%7}, {%8,%9}, {%0,%1,%2,%3};"
        : "+f"(d[0]), "+f"(d[1]), "+f"(d[2]), "+f"(d[3])
        : "r"(a[0]), "r"(a[1]), "r"(a[2]), "r"(a[3]), "r"(b[0]), "r"(b[1]));
}
__device__ __forceinline__ void cpa16(uint32_t dst, const __half* src) {
    asm volatile("cp.async.cg.shared.global [%0], [%1], 16;"
        :: "r"(dst), "l"(__cvta_generic_to_global(src)));
}
#define CP_COMMIT() asm volatile("cp.async.commit_group;" ::: "memory")
#define CP_WAIT2()  asm volatile("cp.async.wait_group 2;" ::: "memory")
#define LDSM4(r0,r1,r2,r3,addr) \
    asm volatile("ldmatrix.sync.aligned.m8n8.x4.shared.b16 {%0,%1,%2,%3}, [%4];" \
        : "=r"(r0), "=r"(r1), "=r"(r2), "=r"(r3) : "r"(addr))

// stage size: 128 rows x 32 halves = 8192 bytes per operand; 4 stages
#define STGB 8192
#define NSTG 4

// ---------------- mainloop: 128x128 tile, KC=32, 4-stage cp.async, ldmatrix ----
__device__ __forceinline__ void mainloop(
    const __half* __restrict__ A, const __half* __restrict__ Bm,
    int K, int m0, int n0, uint32_t sA, uint32_t sB, float acc[4][4][4])
{
    const int tid  = threadIdx.x;
    const int lane = tid & 31;
    const int wid  = tid >> 5;
    const int wm   = (wid >> 2) * 64;
    const int wn   = (wid & 3) * 32;

    const int rA  = tid >> 2;
    const int cA  = tid & 3;
    const int rA2 = rA + 64;
    const uint32_t o0 = rA  * 64 + ((cA ^ ((rA  >> 1) & 3)) * 16);
    const uint32_t o1 = rA2 * 64 + ((cA ^ ((rA2 >> 1) & 3)) * 16);
    const __half* Ag0 = A  + (size_t)(m0 + rA)  * K + cA * 8;
    const __half* Ag1 = A  + (size_t)(m0 + rA2) * K + cA * 8;
    const __half* Bg0 = Bm + (size_t)(n0 + rA)  * K + cA * 8;
    const __half* Bg1 = Bm + (size_t)(n0 + rA2) * K + cA * 8;

    const int rowadd = (lane & 7) + ((lane >> 3) & 1) * 8;
    const int swz    = (rowadd >> 1) & 3;
    const int cbit   = lane >> 4;

    const int NIT = K >> 5;
    #pragma unroll
    for (int s = 0; s < 3; s++) {
        const int k0 = s << 5;
        cpa16(sA + s * STGB + o0, Ag0 + k0);
        cpa16(sA + s * STGB + o1, Ag1 + k0);
        cpa16(sB + s * STGB + o0, Bg0 + k0);
        cpa16(sB + s * STGB + o1, Bg1 + k0);
        CP_COMMIT();
    }
    CP_WAIT2();
    __syncthreads();

    int s = 0;
    for (int it = 0; it < NIT; it++) {
        const uint32_t bA = sA + s * STGB;
        const uint32_t bB = sB + s * STGB;
        #pragma unroll
        for (int kb = 0; kb < 2; kb++) {
            const uint32_t choff = (uint32_t)((((kb << 1) + cbit) ^ swz) * 16);
            const uint32_t aaddr = bA + (wm + rowadd) * 64 + choff;
            const uint32_t baddr = bB + (wn + rowadd) * 64 + choff;
            uint32_t af[4][4], br[2][4];
            #pragma unroll
            for (int mf = 0; mf < 4; mf++)
                LDSM4(af[mf][0], af[mf][1], af[mf][2], af[mf][3], aaddr + mf * 1024);
            #pragma unroll
            for (int nb = 0; nb < 2; nb++)
                LDSM4(br[nb][0], br[nb][1], br[nb][2], br[nb][3], baddr + nb * 1024);
            #pragma unroll
            for (int mf = 0; mf < 4; mf++) {
                #pragma unroll
                for (int nf = 0; nf < 4; nf++) {
                    uint32_t b2[2] = { br[nf >> 1][nf & 1], br[nf >> 1][(nf & 1) + 2] };
                    mma16(acc[mf][nf], af[mf], b2);
                }
            }
        }
        if (it + 3 < NIT) {
            int s2 = s + 3; if (s2 >= NSTG) s2 -= NSTG;
            const int k0 = (it + 3) << 5;
            cpa16(sA + s2 * STGB + o0, Ag0 + k0);
            cpa16(sA + s2 * STGB + o1, Ag1 + k0);
            cpa16(sB + s2 * STGB + o0, Bg0 + k0);
            cpa16(sB + s2 * STGB + o1, Bg1 + k0);
        }
        CP_COMMIT();
        CP_WAIT2();
        __syncthreads();
        if (++s == NSTG) s = 0;
    }
}

#define EPI_NONE 0
#define EPI_TANH 1
#define EPI_SIG  3

__device__ __forceinline__ void zero_acc(float acc[4][4][4]) {
    #pragma unroll
    for (int i = 0; i < 4; i++)
        #pragma unroll
        for (int j = 0; j < 4; j++)
            #pragma unroll
            for (int q = 0; q < 4; q++) acc[i][j][q] = 0.0f;
}

// ---------------- merged K=2048 GEMMs: big-3 (3072 CTAs) + LoRA s1 (320) ------
__global__ __launch_bounds__(256, 2) void gemm_k2048(float* __restrict__ out_r)
{
    __shared__ __half smA[NSTG * STGB / 2];
    __shared__ __half smB[NSTG * STGB / 2];
    const int bid = blockIdx.x;

    const __half* A;
    const __half* Wp;
    float* Of = nullptr;
    __half* Oh = nullptr;
    int m0, n0 = 0, Nst = 2048, epi = EPI_NONE;

    if (bid < 3072) {
        const int g = bid >> 10, rem = bid & 1023;
        m0 = (rem >> 4) * 128;
        n0 = (rem & 15) * 128;
        A  = (g == 0) ? g_xr : (g == 1) ? g_xk : g_xv;
        Wp = (g == 0) ? g_wr : (g == 1) ? g_wk : g_wv;
        Of = (g == 0) ? out_r : (g == 1) ? g_ko : g_vg;
    } else {
        const int sid = bid - 3072;
        const int job = sid >> 6;                 // 0..4
        m0 = (sid & 63) * 128;
        if (job == 0)      { A = g_xw; Wp = g_w1p; Oh = g_hw; Nst = 128; epi = EPI_TANH; }
        else if (job == 1) { A = g_xa; Wp = g_a1p; Oh = g_ha; Nst = 128; }
        else if (job == 2) { A = g_xv; Wp = g_v1p; Oh = g_hv; Nst = 128; }
        else               { A = g_xg; Wp = g_g1p; Oh = g_hg; Nst = 256; epi = EPI_SIG;
                             n0 = (job == 4) ? 128 : 0; }
    }

    float acc[4][4][4];
    zero_acc(acc);
    mainloop(A, Wp, Cdim, m0, n0, smem_u32(smA), smem_u32(smB), acc);

    const int lane = threadIdx.x & 31;
    const int wid  = threadIdx.x >> 5;
    const int wm = (wid >> 2) * 64, wn = (wid & 3) * 32;
    const int tq = lane >> 2, tr = lane & 3;

    if (Of) {
        #pragma unroll
        for (int mf = 0; mf < 4; mf++) {
            #pragma unroll
            for (int nf = 0; nf < 4; nf++) {
                const int n = n0 + wn + nf * 8 + tr * 2;
                #pragma unroll
                for (int h = 0; h < 2; h++) {
                    const int m = m0 + wm + mf * 16 + tq + h * 8;
                    *(float2*)&Of[(size_t)m * 2048 + n] =
                        make_float2(acc[mf][nf][h * 2], acc[mf][nf][h * 2 + 1]);
                }
            }
        }
    } else {
        #pragma unroll
        for (int mf = 0; mf < 4; mf++) {
            #pragma unroll
            for (int nf = 0; nf < 4; nf++) {
                const int n = n0 + wn + nf * 8 + tr * 2;
                #pragma unroll
                for (int h = 0; h < 2; h++) {
                    const int m = m0 + wm + mf * 16 + tq + h * 8;
                    float o0 = acc[mf][nf][h * 2], o1 = acc[mf][nf][h * 2 + 1];
                    if (epi == EPI_TANH)     { o0 = tanhf(o0); o1 = tanhf(o1); }
                    else if (epi == EPI_SIG) { o0 = sigmoidf_(o0); o1 = sigmoidf_(o1); }
                    *(__half2*)&Oh[(size_t)m * Nst + n] = __floats2half2_rn(o0, o1);
                }
            }
        }
    }
}

// ---------------- LoRA stage-2 (z-merged; z==1 fuses a + k_final + kk) --------
__global__ __launch_bounds__(256, 2) void gemm_s2(
    float* __restrict__ out_w, float* __restrict__ out_a,
    float* __restrict__ out_v, float* __restrict__ out_g,
    float* __restrict__ out_k, float* __restrict__ out_kk,
    const float* __restrict__ w0, const float* __restrict__ a0,
    const float* __restrict__ v0, const float* __restrict__ vfp,
    const float* __restrict__ k_k, const float* __restrict__ k_a)
{
    __shared__ __half smA[NSTG * STGB / 2];
    __shared__ __half smB[NSTG * STGB / 2];
    __shared__ float smRed[8][64];
    const int z = blockIdx.z;
    const __half* A;
    const __half* Wp;
    float* O;
    const float* bias = nullptr;
    int K, epi;  // epi: 0=W, 1=fused-a, 2=vmix, 3=none
    if (z == 0)      { A = g_hw; Wp = g_w2p; O = out_w; K = 128; epi = 0; bias = w0; }
    else if (z == 1) { A = g_ha; Wp = g_a2p; O = out_a; K = 128; epi = 1; bias = a0; }
    else if (z == 2) { A = g_hv; Wp = g_v2p; O = out_v; K = 128; epi = 2; bias = v0; }
    else             { A = g_hg; Wp = g_g2p; O = out_g; K = 256; epi = 3; }

    const int n0 = blockIdx.x * 128;
    const int m0 = blockIdx.y * 128;
    float acc[4][4][4];
    zero_acc(acc);
    mainloop(A, Wp, K, m0, n0, smem_u32(smA), smem_u32(smB), acc);

    const int lane = threadIdx.x & 31;
    const int wid  = threadIdx.x >> 5;
    const int wm = (wid >> 2) * 64, wn = (wid & 3) * 32;
    const int tq = lane >> 2, tr = lane & 3;

    if (epi == 1) {
        // fused: a = sigmoid(a0+acc); k_final = ko*(1+(a-1)*k_a); kk = normalize(ko*k_k)
        float ss[4][2] = {};
        #pragma unroll
        for (int mf = 0; mf < 4; mf++) {
            #pragma unroll
            for (int nf = 0; nf < 4; nf++) {
                const int n = n0 + wn + nf * 8 + tr * 2;
                const float bv0 = bias[n], bv1 = bias[n + 1];
                const float kc0 = k_k[n], kc1 = k_k[n + 1];
                const float ka0 = k_a[n], ka1 = k_a[n + 1];
                #pragma unroll
                for (int h = 0; h < 2; h++) {
                    const int m = m0 + wm + mf * 16 + tq + h * 8;
                    const size_t ix = (size_t)m * Cdim + n;
                    float a0v = sigmoidf_(acc[mf][nf][h * 2]     + bv0);
                    float a1v = sigmoidf_(acc[mf][nf][h * 2 + 1] + bv1);
                    *(float2*)&out_a[ix] = make_float2(a0v, a1v);
                    float2 kr = *(const float2*)&g_ko[ix];
                    *(float2*)&out_k[ix] = make_float2(
                        kr.x * fmaf(a0v - 1.0f, ka0, 1.0f),
                        kr.y * fmaf(a1v - 1.0f, ka1, 1.0f));
                    float kk0 = kr.x * kc0, kk1 = kr.y * kc1;
                    ss[mf][h] += kk0 * kk0 + kk1 * kk1;
                }
            }
        }
        #pragma unroll
        for (int mf = 0; mf < 4; mf++)
            #pragma unroll
            for (int h = 0; h < 2; h++) {
                ss[mf][h] += __shfl_xor_sync(0xFFFFFFFFu, ss[mf][h], 1);
                ss[mf][h] += __shfl_xor_sync(0xFFFFFFFFu, ss[mf][h], 2);
            }
        if (tr == 0) {
            #pragma unroll
            for (int mf = 0; mf < 4; mf++)
                #pragma unroll
                for (int h = 0; h < 2; h++)
                    smRed[wid][mf * 16 + h * 8 + tq] = ss[mf][h];
        }
        __syncthreads();
        float inv[4][2];
        #pragma unroll
        for (int mf = 0; mf < 4; mf++)
            #pragma unroll
            for (int h = 0; h < 2; h++) {
                const int ml = mf * 16 + h * 8 + tq;
                float t = smRed[wid][ml] + smRed[wid ^ 1][ml];
                inv[mf][h] = 1.0f / fmaxf(sqrtf(t), 1e-12f);
            }
        #pragma unroll
        for (int mf = 0; mf < 4; mf++) {
            #pragma unroll
            for (int nf = 0; nf < 4; nf++) {
                const int n = n0 + wn + nf * 8 + tr * 2;
                const float kc0 = k_k[n], kc1 = k_k[n + 1];
                #pragma unroll
                for (int h = 0; h < 2; h++) {
                    const int m = m0 + wm + mf * 16 + tq + h * 8;
                    const size_t ix = (size_t)m * Cdim + n;
                    float2 kr = *(const float2*)&g_ko[ix];
                    *(float2*)&out_kk[ix] = make_float2(
                        kr.x * kc0 * inv[mf][h], kr.y * kc1 * inv[mf][h]);
                }
            }
        }
        return;
    }

    #pragma unroll
    for (int mf = 0; mf < 4; mf++) {
        #pragma unroll
        for (int nf = 0; nf < 4; nf++) {
            const int n = n0 + wn + nf * 8 + tr * 2;
            float bv0 = 0.0f, bv1 = 0.0f;
            if (bias) { bv0 = bias[n]; bv1 = bias[n + 1]; }
            #pragma unroll
            for (int h = 0; h < 2; h++) {
                const int m = m0 + wm + mf * 16 + tq + h * 8;
                float v0c = acc[mf][nf][h * 2], v1c = acc[mf][nf][h * 2 + 1];
                float o0, o1;
                if (epi == 0) {
                    float y0 = bv0 + v0c, y1 = bv1 + v1c;
                    o0 = -(fmaxf(-y0, 0.0f) + log1pf(expf(-fabsf(y0)))) - 0.5f;
                    o1 = -(fmaxf(-y1, 0.0f) + log1pf(expf(-fabsf(y1)))) - 0.5f;
                } else if (epi == 2) {
                    float s0 = sigmoidf_(bv0 + v0c), s1 = sigmoidf_(bv1 + v1c);
                    size_t ix = (size_t)m * Cdim + n;
                    float vg0 = g_vg[ix], vg1 = g_vg[ix + 1];
                    o0 = vg0 + (vfp[ix] - vg0) * s0;
                    o1 = vg1 + (vfp[ix + 1] - vg1) * s1;
                } else { o0 = v0c; o1 = v1c; }
                *(float2*)&O[(size_t)m * Cdim + n] = make_float2(o0, o1);
            }
        }
    }
}

// ---------------- merged prologue: mix + prep_big + prep_l1t + prep_l2t -------
// bid ranges: [0,16384) mix | [16384,28672) prep_big | [28672,30720) l1t | [30720,32768) l2t
__global__ __launch_bounds__(256) void prologue(
    const float* __restrict__ x, const float* __restrict__ vf,
    const float* __restrict__ mr, const float* __restrict__ mw,
    const float* __restrict__ mk, const float* __restrict__ mv,
    const float* __restrict__ ma, const float* __restrict__ mg,
    float* __restrict__ out_vf,
    const float* __restrict__ Wr, const float* __restrict__ Wk, const float* __restrict__ Wv,
    const float* __restrict__ w1, const float* __restrict__ a1,
    const float* __restrict__ v1, const float* __restrict__ g1,
    const float* __restrict__ w2, const float* __restrict__ a2,
    const float* __restrict__ v2, const float* __restrict__ g2)
{
    __shared__ float sm[32][33];
    const int bid = blockIdx.x;
    const int tid = threadIdx.x;

    if (bid < 16384) {
        // ---- mix ----
        size_t idx = ((size_t)bid * 256 + tid) * 4;
        int c   = (int)(idx & (Cdim - 1));
        int row = (int)(idx >> 11);
        int t   = row & (Tdim - 1);
        float4 xc = *(const float4*)&x[idx];
        float4 xp = (t == 0) ? make_float4(0.f, 0.f, 0.f, 0.f) : *(const float4*)&x[idx - Cdim];
        float4 xx = make_float4(xp.x - xc.x, xp.y - xc.y, xp.z - xc.z, xp.w - xc.w);
        *(float4*)&out_vf[idx] = *(const float4*)&vf[idx];
        #define DOMIX(dst, mm) do { \
            float4 mv_ = *(const float4*)&mm[c]; \
            __half2 h0_ = __floats2half2_rn(fmaf(xx.x, mv_.x, xc.x), fmaf(xx.y, mv_.y, xc.y)); \
            __half2 h1_ = __floats2half2_rn(fmaf(xx.z, mv_.z, xc.z), fmaf(xx.w, mv_.w, xc.w)); \
            uint2 u_; u_.x = *(uint32_t*)&h0_; u_.y = *(uint32_t*)&h1_; \
            *(uint2*)&dst[idx] = u_; \
        } while (0)
        DOMIX(g_xr, mr); DOMIX(g_xw, mw); DOMIX(g_xk, mk);
        DOMIX(g_xv, mv); DOMIX(g_xa, ma); DOMIX(g_xg, mg);
        #undef DOMIX
    } else if (bid < 28672) {
        // ---- prep_big ----
        const int pb = bid - 16384;
        const int z = pb >> 12;                  // 0..2
        size_t idx = ((size_t)(pb & 4095) * 256 + tid) * 4;
        const float* W = (z == 0) ? Wr : (z == 1) ? Wk : Wv;
        __half* P = (z == 0) ? g_wr : (z == 1) ? g_wk : g_wv;
        float4 wv = *(const float4*)&W[idx];
        __half2 h0 = __floats2half2_rn(wv.x, wv.y);
        __half2 h1 = __floats2half2_rn(wv.z, wv.w);
        uint2 u; u.x = *(uint32_t*)&h0; u.y = *(uint32_t*)&h1;
        *(uint2*)&P[idx] = u;
    } else if (bid < 30720) {
        // ---- prep_l1t: src [C, D_] -> dst [Dp, C] ----
        const int sid = bid - 28672;
        const int z = sid >> 9;                   // 0..3
        const int r = sid & 511;
        const int by = r >> 6, bx = r & 63;       // y in [0,8), x in [0,64)
        const float* src = (z == 0) ? w1 : (z == 1) ? a1 : (z == 2) ? v1 : g1;
        __half* dst = (z == 0) ? g_w1p : (z == 1) ? g_a1p : (z == 2) ? g_v1p : g_g1p;
        const int D_ = (z == 0) ? 128 : (z == 1) ? 128 : (z == 2) ? 64 : 224;
        const int Dp = (z == 3) ? 256 : 128;
        const int nn_t = by * 32;
        if (nn_t < Dp) {
            const int k_t = bx * 32;
            const int tx = tid & 31, ty = tid >> 5;
            #pragma unroll
            for (int i = 0; i < 4; i++) {
                const int k = k_t + ty + i * 8;
                const int nn = nn_t + tx;
                sm[ty + i * 8][tx] = (nn < D_) ? src[(size_t)k * D_ + nn] : 0.0f;
            }
            __syncthreads();
            #pragma unroll
            for (int i = 0; i < 4; i++) {
                const int nn = nn_t + ty + i * 8;
                const int k = k_t + tx;
                dst[(size_t)nn * Cdim + k] = __float2half(sm[tx][ty + i * 8]);
            }
        }
    } else {
        // ---- prep_l2t: src [D_, C] -> dst [C, Dp] ----
        const int sid = bid - 30720;
        const int z = sid >> 9;
        const int r = sid & 511;
        const int by = r >> 6, bx = r & 63;
        const float* src = (z == 0) ? w2 : (z == 1) ? a2 : (z == 2) ? v2 : g2;
        __half* dst = (z == 0) ? g_w2p : (z == 1) ? g_a2p : (z == 2) ? g_v2p : g_g2p;
        const int D_ = (z == 0) ? 128 : (z == 1) ? 128 : (z == 2) ? 64 : 224;
        const int Dp = (z == 3) ? 256 : 128;
        const int d_t = by * 32;
        if (d_t < Dp) {
            const int nn_t = bx * 32;
            const int tx = tid & 31, ty = tid >> 5;
            #pragma unroll
            for (int i = 0; i < 4; i++) {
                const int d = d_t + ty + i * 8;
                const int nn = nn_t + tx;
                sm[ty + i * 8][tx] = (d < D_) ? src[(size_t)d * Cdim + nn] : 0.0f;
            }
            __syncthreads();
            #pragma unroll
            for (int i = 0; i < 4; i++) {
                const int nn = nn_t + ty + i * 8;
                const int d = d_t + tx;
                dst[(size_t)nn * Dp + d] = __float2half(sm[tx][ty + i * 8]);
            }
        }
    }
}

// ---------------- launch ----------------
extern "C" void kernel_launch(void* const* d_in, const int* in_sizes, int n_in,
                              void* d_out, int out_size)
{
    const float* x   = (const float*)d_in[0];
    const float* vf  = (const float*)d_in[1];
    const float* x_r = (const float*)d_in[2];
    const float* x_w = (const float*)d_in[3];
    const float* x_k = (const float*)d_in[4];
    const float* x_v = (const float*)d_in[5];
    const float* x_a = (const float*)d_in[6];
    const float* x_g = (const float*)d_in[7];
    const float* w0  = (const float*)d_in[8];
    const float* w1  = (const float*)d_in[9];
    const float* w2  = (const float*)d_in[10];
    const float* a0  = (const float*)d_in[11];
    const float* a1  = (const float*)d_in[12];
    const float* a2  = (const float*)d_in[13];
    const float* v0  = (const float*)d_in[14];
    const float* v1  = (const float*)d_in[15];
    const float* v2  = (const float*)d_in[16];
    const float* g1  = (const float*)d_in[17];
    const float* g2  = (const float*)d_in[18];
    const float* k_k = (const float*)d_in[19];
    const float* k_a = (const float*)d_in[20];
    const float* Wr  = (const float*)d_in[21];
    const float* Wk  = (const float*)d_in[22];
    const float* Wv  = (const float*)d_in[23];
    (void)in_sizes; (void)n_in; (void)out_size;

    float* out = (float*)d_out;
    float* out_r  = out + 0 * BTC;
    float* out_w  = out + 1 * BTC;
    float* out_k  = out + 2 * BTC;
    float* out_v  = out + 3 * BTC;
    float* out_a  = out + 4 * BTC;
    float* out_g  = out + 5 * BTC;
    float* out_kk = out + 6 * BTC;
    float* out_vf = out + 7 * BTC;

    // 1. merged prologue (mix + all weight preps) in one flat launch
    prologue<<<32768, 256>>>(x, vf, x_r, x_w, x_k, x_v, x_a, x_g, out_vf,
                             Wr, Wk, Wv, w1, a1, v1, g1, w2, a2, v2, g2);

    // 2. all K=2048 GEMMs in one flat launch (big-3 first, s1 in the tail wave)
    gemm_k2048<<<3392, 256>>>(out_r);

    // 3. LoRA stage 2 (merged, fused epilogues; z==1 also emits k_final + kk)
    gemm_s2<<<dim3(Cdim / 128, Mrows / 128, 4), 256>>>(
        out_w, out_a, out_v, out_g, out_k, out_kk, w0, a0, v0, vf, k_k, k_a);
}

// round 17
// speedup vs baseline: 1.0476x; 1.0196x over previous
#include <cuda_runtime.h>
#include <cuda_fp16.h>
#include <math.h>
#include <stdint.h>

#define Bdim 2
#define Tdim 4096
#define Cdim 2048
#define HSZ  64
#define Mrows 8192
static const size_t BTC = (size_t)Mrows * Cdim;

// ---------------- scratch ----------------
__device__ __half g_xr[(size_t)Mrows * Cdim];
__device__ __half g_xw[(size_t)Mrows * Cdim];
__device__ __half g_xk[(size_t)Mrows * Cdim];
__device__ __half g_xv[(size_t)Mrows * Cdim];
__device__ __half g_xa[(size_t)Mrows * Cdim];
__device__ __half g_xg[(size_t)Mrows * Cdim];
__device__ __half g_wr[(size_t)Cdim * Cdim];
__device__ __half g_wk[(size_t)Cdim * Cdim];
__device__ __half g_wv[(size_t)Cdim * Cdim];
__device__ __half g_w1p[(size_t)128 * Cdim];
__device__ __half g_a1p[(size_t)128 * Cdim];
__device__ __half g_v1p[(size_t)128 * Cdim];
__device__ __half g_g1p[(size_t)256 * Cdim];
__device__ __half g_w2p[(size_t)Cdim * 128];
__device__ __half g_a2p[(size_t)Cdim * 128];
__device__ __half g_v2p[(size_t)Cdim * 128];
__device__ __half g_g2p[(size_t)Cdim * 256];
__device__ __half g_hw[(size_t)Mrows * 128];
__device__ __half g_ha[(size_t)Mrows * 128];
__device__ __half g_hv[(size_t)Mrows * 128];
__device__ __half g_hg[(size_t)Mrows * 256];
__device__ __half g_ko[(size_t)Mrows * Cdim];   // fp16 scratch
__device__ __half g_vg[(size_t)Mrows * Cdim];   // fp16 scratch

// ---------------- helpers ----------------
__device__ __forceinline__ float sigmoidf_(float y) { return 1.0f / (1.0f + expf(-y)); }

__device__ __forceinline__ uint32_t smem_u32(const void* p) {
    uint32_t a;
    asm("{ .reg .u64 t; cvta.to.shared.u64 t, %1; cvt.u32.u64 %0, t; }" : "=r"(a) : "l"(p));
    return a;
}
__device__ __forceinline__ void mma16(float* d, const uint32_t* a, const uint32_t* b) {
    asm volatile("mma.sync.aligned.m16n8k16.row.col.f32.f16.f16.f32 "
        "{%0,%1,%2,%3}, {%4,%5,%6,%7}, {%8,%9}, {%0,%1,%2,%3};"
        : "+f"(d[0]), "+f"(d[1]), "+f"(d[2]), "+f"(d[3])
        : "r"(a[0]), "r"(a[1]), "r"(a[2]), "r"(a[3]), "r"(b[0]), "r"(b[1]));
}
__device__ __forceinline__ void cpa16(uint32_t dst, const __half* src) {
    asm volatile("cp.async.cg.shared.global [%0], [%1], 16;"
        :: "r"(dst), "l"(__cvta_generic_to_global(src)));
}
#define CP_COMMIT() asm volatile("cp.async.commit_group;" ::: "memory")
#define CP_WAIT2()  asm volatile("cp.async.wait_group 2;" ::: "memory")
#define LDSM4(r0,r1,r2,r3,addr) \
    asm volatile("ldmatrix.sync.aligned.m8n8.x4.shared.b16 {%0,%1,%2,%3}, [%4];" \
        : "=r"(r0), "=r"(r1), "=r"(r2), "=r"(r3) : "r"(addr))

// stage size: 128 rows x 32 halves = 8192 bytes per operand; 4 stages
#define STGB 8192
#define NSTG 4

// ---------------- mainloop: 128x128 tile, KC=32, 4-stage cp.async, ldmatrix ----
__device__ __forceinline__ void mainloop(
    const __half* __restrict__ A, const __half* __restrict__ Bm,
    int K, int m0, int n0, uint32_t sA, uint32_t sB, float acc[4][4][4])
{
    const int tid  = threadIdx.x;
    const int lane = tid & 31;
    const int wid  = tid >> 5;
    const int wm   = (wid >> 2) * 64;
    const int wn   = (wid & 3) * 32;

    const int rA  = tid >> 2;
    const int cA  = tid & 3;
    const int rA2 = rA + 64;
    const uint32_t o0 = rA  * 64 + ((cA ^ ((rA  >> 1) & 3)) * 16);
    const uint32_t o1 = rA2 * 64 + ((cA ^ ((rA2 >> 1) & 3)) * 16);
    const __half* Ag0 = A  + (size_t)(m0 + rA)  * K + cA * 8;
    const __half* Ag1 = A  + (size_t)(m0 + rA2) * K + cA * 8;
    const __half* Bg0 = Bm + (size_t)(n0 + rA)  * K + cA * 8;
    const __half* Bg1 = Bm + (size_t)(n0 + rA2) * K + cA * 8;

    const int rowadd = (lane & 7) + ((lane >> 3) & 1) * 8;
    const int swz    = (rowadd >> 1) & 3;
    const int cbit   = lane >> 4;

    const int NIT = K >> 5;
    #pragma unroll
    for (int s = 0; s < 3; s++) {
        const int k0 = s << 5;
        cpa16(sA + s * STGB + o0, Ag0 + k0);
        cpa16(sA + s * STGB + o1, Ag1 + k0);
        cpa16(sB + s * STGB + o0, Bg0 + k0);
        cpa16(sB + s * STGB + o1, Bg1 + k0);
        CP_COMMIT();
    }
    CP_WAIT2();
    __syncthreads();

    int s = 0;
    for (int it = 0; it < NIT; it++) {
        const uint32_t bA = sA + s * STGB;
        const uint32_t bB = sB + s * STGB;
        #pragma unroll
        for (int kb = 0; kb < 2; kb++) {
            const uint32_t choff = (uint32_t)((((kb << 1) + cbit) ^ swz) * 16);
            const uint32_t aaddr = bA + (wm + rowadd) * 64 + choff;
            const uint32_t baddr = bB + (wn + rowadd) * 64 + choff;
            uint32_t af[4][4], br[2][4];
            #pragma unroll
            for (int mf = 0; mf < 4; mf++)
                LDSM4(af[mf][0], af[mf][1], af[mf][2], af[mf][3], aaddr + mf * 1024);
            #pragma unroll
            for (int nb = 0; nb < 2; nb++)
                LDSM4(br[nb][0], br[nb][1], br[nb][2], br[nb][3], baddr + nb * 1024);
            #pragma unroll
            for (int mf = 0; mf < 4; mf++) {
                #pragma unroll
                for (int nf = 0; nf < 4; nf++) {
                    uint32_t b2[2] = { br[nf >> 1][nf & 1], br[nf >> 1][(nf & 1) + 2] };
                    mma16(acc[mf][nf], af[mf], b2);
                }
            }
        }
        if (it + 3 < NIT) {
            int s2 = s + 3; if (s2 >= NSTG) s2 -= NSTG;
            const int k0 = (it + 3) << 5;
            cpa16(sA + s2 * STGB + o0, Ag0 + k0);
            cpa16(sA + s2 * STGB + o1, Ag1 + k0);
            cpa16(sB + s2 * STGB + o0, Bg0 + k0);
            cpa16(sB + s2 * STGB + o1, Bg1 + k0);
        }
        CP_COMMIT();
        CP_WAIT2();
        __syncthreads();
        if (++s == NSTG) s = 0;
    }
}

#define EPI_NONE 0
#define EPI_TANH 1
#define EPI_SIG  3

__device__ __forceinline__ void zero_acc(float acc[4][4][4]) {
    #pragma unroll
    for (int i = 0; i < 4; i++)
        #pragma unroll
        for (int j = 0; j < 4; j++)
            #pragma unroll
            for (int q = 0; q < 4; q++) acc[i][j][q] = 0.0f;
}

// ---------------- merged K=2048 GEMMs: big-3 (3072 CTAs) + LoRA s1 (320) ------
__global__ __launch_bounds__(256, 2) void gemm_k2048(float* __restrict__ out_r)
{
    __shared__ __half smA[NSTG * STGB / 2];
    __shared__ __half smB[NSTG * STGB / 2];
    const int bid = blockIdx.x;

    const __half* A;
    const __half* Wp;
    float* Of = nullptr;
    __half* Oh = nullptr;
    int m0, n0 = 0, Nst = 2048, epi = EPI_NONE;

    if (bid < 3072) {
        const int g = bid >> 10, rem = bid & 1023;
        m0 = (rem >> 4) * 128;
        n0 = (rem & 15) * 128;
        A  = (g == 0) ? g_xr : (g == 1) ? g_xk : g_xv;
        Wp = (g == 0) ? g_wr : (g == 1) ? g_wk : g_wv;
        if (g == 0) Of = out_r;
        else        Oh = (g == 1) ? g_ko : g_vg;   // fp16 scratch, Nst=2048
    } else {
        const int sid = bid - 3072;
        const int job = sid >> 6;                 // 0..4
        m0 = (sid & 63) * 128;
        if (job == 0)      { A = g_xw; Wp = g_w1p; Oh = g_hw; Nst = 128; epi = EPI_TANH; }
        else if (job == 1) { A = g_xa; Wp = g_a1p; Oh = g_ha; Nst = 128; }
        else if (job == 2) { A = g_xv; Wp = g_v1p; Oh = g_hv; Nst = 128; }
        else               { A = g_xg; Wp = g_g1p; Oh = g_hg; Nst = 256; epi = EPI_SIG;
                             n0 = (job == 4) ? 128 : 0; }
    }

    float acc[4][4][4];
    zero_acc(acc);
    mainloop(A, Wp, Cdim, m0, n0, smem_u32(smA), smem_u32(smB), acc);

    const int lane = threadIdx.x & 31;
    const int wid  = threadIdx.x >> 5;
    const int wm = (wid >> 2) * 64, wn = (wid & 3) * 32;
    const int tq = lane >> 2, tr = lane & 3;

    if (Of) {
        #pragma unroll
        for (int mf = 0; mf < 4; mf++) {
            #pragma unroll
            for (int nf = 0; nf < 4; nf++) {
                const int n = n0 + wn + nf * 8 + tr * 2;
                #pragma unroll
                for (int h = 0; h < 2; h++) {
                    const int m = m0 + wm + mf * 16 + tq + h * 8;
                    *(float2*)&Of[(size_t)m * 2048 + n] =
                        make_float2(acc[mf][nf][h * 2], acc[mf][nf][h * 2 + 1]);
                }
            }
        }
    } else {
        #pragma unroll
        for (int mf = 0; mf < 4; mf++) {
            #pragma unroll
            for (int nf = 0; nf < 4; nf++) {
                const int n = n0 + wn + nf * 8 + tr * 2;
                #pragma unroll
                for (int h = 0; h < 2; h++) {
                    const int m = m0 + wm + mf * 16 + tq + h * 8;
                    float o0 = acc[mf][nf][h * 2], o1 = acc[mf][nf][h * 2 + 1];
                    if (epi == EPI_TANH)     { o0 = tanhf(o0); o1 = tanhf(o1); }
                    else if (epi == EPI_SIG) { o0 = sigmoidf_(o0); o1 = sigmoidf_(o1); }
                    *(__half2*)&Oh[(size_t)m * Nst + n] = __floats2half2_rn(o0, o1);
                }
            }
        }
    }
}

// ---------------- LoRA stage-2 (z-merged; z==1 fuses a + k_final + kk) --------
__global__ __launch_bounds__(256, 2) void gemm_s2(
    float* __restrict__ out_w, float* __restrict__ out_a,
    float* __restrict__ out_v, float* __restrict__ out_g,
    float* __restrict__ out_k, float* __restrict__ out_kk,
    const float* __restrict__ w0, const float* __restrict__ a0,
    const float* __restrict__ v0, const float* __restrict__ vfp,
    const float* __restrict__ k_k, const float* __restrict__ k_a)
{
    __shared__ __half smA[NSTG * STGB / 2];
    __shared__ __half smB[NSTG * STGB / 2];
    __shared__ float smRed[8][64];
    const int z = blockIdx.z;
    const __half* A;
    const __half* Wp;
    float* O;
    const float* bias = nullptr;
    int K, epi;  // epi: 0=W, 1=fused-a, 2=vmix, 3=none
    if (z == 0)      { A = g_hw; Wp = g_w2p; O = out_w; K = 128; epi = 0; bias = w0; }
    else if (z == 1) { A = g_ha; Wp = g_a2p; O = out_a; K = 128; epi = 1; bias = a0; }
    else if (z == 2) { A = g_hv; Wp = g_v2p; O = out_v; K = 128; epi = 2; bias = v0; }
    else             { A = g_hg; Wp = g_g2p; O = out_g; K = 256; epi = 3; }

    const int n0 = blockIdx.x * 128;
    const int m0 = blockIdx.y * 128;
    float acc[4][4][4];
    zero_acc(acc);
    mainloop(A, Wp, K, m0, n0, smem_u32(smA), smem_u32(smB), acc);

    const int lane = threadIdx.x & 31;
    const int wid  = threadIdx.x >> 5;
    const int wm = (wid >> 2) * 64, wn = (wid & 3) * 32;
    const int tq = lane >> 2, tr = lane & 3;

    if (epi == 1) {
        // fused: a = sigmoid(a0+acc); k_final = ko*(1+(a-1)*k_a); kk = normalize(ko*k_k)
        // pass 1 overwrites acc with kk values (acc dead after a is computed)
        float ss[4][2] = {};
        #pragma unroll
        for (int mf = 0; mf < 4; mf++) {
            #pragma unroll
            for (int nf = 0; nf < 4; nf++) {
                const int n = n0 + wn + nf * 8 + tr * 2;
                const float bv0 = bias[n], bv1 = bias[n + 1];
                const float kc0 = k_k[n], kc1 = k_k[n + 1];
                const float ka0 = k_a[n], ka1 = k_a[n + 1];
                #pragma unroll
                for (int h = 0; h < 2; h++) {
                    const int m = m0 + wm + mf * 16 + tq + h * 8;
                    const size_t ix = (size_t)m * Cdim + n;
                    float a0v = sigmoidf_(acc[mf][nf][h * 2]     + bv0);
                    float a1v = sigmoidf_(acc[mf][nf][h * 2 + 1] + bv1);
                    *(float2*)&out_a[ix] = make_float2(a0v, a1v);
                    float2 kr = __half22float2(*(const __half2*)&g_ko[ix]);
                    *(float2*)&out_k[ix] = make_float2(
                        kr.x * fmaf(a0v - 1.0f, ka0, 1.0f),
                        kr.y * fmaf(a1v - 1.0f, ka1, 1.0f));
                    float kk0 = kr.x * kc0, kk1 = kr.y * kc1;
                    ss[mf][h] += kk0 * kk0 + kk1 * kk1;
                    acc[mf][nf][h * 2]     = kk0;   // carry kk in dead acc regs
                    acc[mf][nf][h * 2 + 1] = kk1;
                }
            }
        }
        #pragma unroll
        for (int mf = 0; mf < 4; mf++)
            #pragma unroll
            for (int h = 0; h < 2; h++) {
                ss[mf][h] += __shfl_xor_sync(0xFFFFFFFFu, ss[mf][h], 1);
                ss[mf][h] += __shfl_xor_sync(0xFFFFFFFFu, ss[mf][h], 2);
            }
        if (tr == 0) {
            #pragma unroll
            for (int mf = 0; mf < 4; mf++)
                #pragma unroll
                for (int h = 0; h < 2; h++)
                    smRed[wid][mf * 16 + h * 8 + tq] = ss[mf][h];
        }
        __syncthreads();
        float inv[4][2];
        #pragma unroll
        for (int mf = 0; mf < 4; mf++)
            #pragma unroll
            for (int h = 0; h < 2; h++) {
                const int ml = mf * 16 + h * 8 + tq;
                float t = smRed[wid][ml] + smRed[wid ^ 1][ml];
                inv[mf][h] = 1.0f / fmaxf(sqrtf(t), 1e-12f);
            }
        #pragma unroll
        for (int mf = 0; mf < 4; mf++) {
            #pragma unroll
            for (int nf = 0; nf < 4; nf++) {
                const int n = n0 + wn + nf * 8 + tr * 2;
                #pragma unroll
                for (int h = 0; h < 2; h++) {
                    const int m = m0 + wm + mf * 16 + tq + h * 8;
                    const size_t ix = (size_t)m * Cdim + n;
                    *(float2*)&out_kk[ix] = make_float2(
                        acc[mf][nf][h * 2]     * inv[mf][h],
                        acc[mf][nf][h * 2 + 1] * inv[mf][h]);
                }
            }
        }
        return;
    }

    #pragma unroll
    for (int mf = 0; mf < 4; mf++) {
        #pragma unroll
        for (int nf = 0; nf < 4; nf++) {
            const int n = n0 + wn + nf * 8 + tr * 2;
            float bv0 = 0.0f, bv1 = 0.0f;
            if (bias) { bv0 = bias[n]; bv1 = bias[n + 1]; }
            #pragma unroll
            for (int h = 0; h < 2; h++) {
                const int m = m0 + wm + mf * 16 + tq + h * 8;
                float v0c = acc[mf][nf][h * 2], v1c = acc[mf][nf][h * 2 + 1];
                float o0, o1;
                if (epi == 0) {
                    float y0 = bv0 + v0c, y1 = bv1 + v1c;
                    o0 = -(fmaxf(-y0, 0.0f) + log1pf(expf(-fabsf(y0)))) - 0.5f;
                    o1 = -(fmaxf(-y1, 0.0f) + log1pf(expf(-fabsf(y1)))) - 0.5f;
                } else if (epi == 2) {
                    float s0 = sigmoidf_(bv0 + v0c), s1 = sigmoidf_(bv1 + v1c);
                    size_t ix = (size_t)m * Cdim + n;
                    float2 vg2 = __half22float2(*(const __half2*)&g_vg[ix]);
                    o0 = vg2.x + (vfp[ix] - vg2.x) * s0;
                    o1 = vg2.y + (vfp[ix + 1] - vg2.y) * s1;
                } else { o0 = v0c; o1 = v1c; }
                *(float2*)&O[(size_t)m * Cdim + n] = make_float2(o0, o1);
            }
        }
    }
}

// ---------------- merged prologue: mix + prep_big + prep_l1t + prep_l2t -------
// bid ranges: [0,16384) mix | [16384,28672) prep_big | [28672,30720) l1t | [30720,32768) l2t
__global__ __launch_bounds__(256) void prologue(
    const float* __restrict__ x, const float* __restrict__ vf,
    const float* __restrict__ mr, const float* __restrict__ mw,
    const float* __restrict__ mk, const float* __restrict__ mv,
    const float* __restrict__ ma, const float* __restrict__ mg,
    float* __restrict__ out_vf,
    const float* __restrict__ Wr, const float* __restrict__ Wk, const float* __restrict__ Wv,
    const float* __restrict__ w1, const float* __restrict__ a1,
    const float* __restrict__ v1, const float* __restrict__ g1,
    const float* __restrict__ w2, const float* __restrict__ a2,
    const float* __restrict__ v2, const float* __restrict__ g2)
{
    __shared__ float sm[32][33];
    const int bid = blockIdx.x;
    const int tid = threadIdx.x;

    if (bid < 16384) {
        // ---- mix ----
        size_t idx = ((size_t)bid * 256 + tid) * 4;
        int c   = (int)(idx & (Cdim - 1));
        int row = (int)(idx >> 11);
        int t   = row & (Tdim - 1);
        float4 xc = *(const float4*)&x[idx];
        float4 xp = (t == 0) ? make_float4(0.f, 0.f, 0.f, 0.f) : *(const float4*)&x[idx - Cdim];
        float4 xx = make_float4(xp.x - xc.x, xp.y - xc.y, xp.z - xc.z, xp.w - xc.w);
        *(float4*)&out_vf[idx] = *(const float4*)&vf[idx];
        #define DOMIX(dst, mm) do { \
            float4 mv_ = *(const float4*)&mm[c]; \
            __half2 h0_ = __floats2half2_rn(fmaf(xx.x, mv_.x, xc.x), fmaf(xx.y, mv_.y, xc.y)); \
            __half2 h1_ = __floats2half2_rn(fmaf(xx.z, mv_.z, xc.z), fmaf(xx.w, mv_.w, xc.w)); \
            uint2 u_; u_.x = *(uint32_t*)&h0_; u_.y = *(uint32_t*)&h1_; \
            *(uint2*)&dst[idx] = u_; \
        } while (0)
        DOMIX(g_xr, mr); DOMIX(g_xw, mw); DOMIX(g_xk, mk);
        DOMIX(g_xv, mv); DOMIX(g_xa, ma); DOMIX(g_xg, mg);
        #undef DOMIX
    } else if (bid < 28672) {
        // ---- prep_big ----
        const int pb = bid - 16384;
        const int z = pb >> 12;                  // 0..2
        size_t idx = ((size_t)(pb & 4095) * 256 + tid) * 4;
        const float* W = (z == 0) ? Wr : (z == 1) ? Wk : Wv;
        __half* P = (z == 0) ? g_wr : (z == 1) ? g_wk : g_wv;
        float4 wv = *(const float4*)&W[idx];
        __half2 h0 = __floats2half2_rn(wv.x, wv.y);
        __half2 h1 = __floats2half2_rn(wv.z, wv.w);
        uint2 u; u.x = *(uint32_t*)&h0; u.y = *(uint32_t*)&h1;
        *(uint2*)&P[idx] = u;
    } else if (bid < 30720) {
        // ---- prep_l1t: src [C, D_] -> dst [Dp, C] ----
        const int sid = bid - 28672;
        const int z = sid >> 9;                   // 0..3
        const int r = sid & 511;
        const int by = r >> 6, bx = r & 63;       // y in [0,8), x in [0,64)
        const float* src = (z == 0) ? w1 : (z == 1) ? a1 : (z == 2) ? v1 : g1;
        __half* dst = (z == 0) ? g_w1p : (z == 1) ? g_a1p : (z == 2) ? g_v1p : g_g1p;
        const int D_ = (z == 0) ? 128 : (z == 1) ? 128 : (z == 2) ? 64 : 224;
        const int Dp = (z == 3) ? 256 : 128;
        const int nn_t = by * 32;
        if (nn_t < Dp) {
            const int k_t = bx * 32;
            const int tx = tid & 31, ty = tid >> 5;
            #pragma unroll
            for (int i = 0; i < 4; i++) {
                const int k = k_t + ty + i * 8;
                const int nn = nn_t + tx;
                sm[ty + i * 8][tx] = (nn < D_) ? src[(size_t)k * D_ + nn] : 0.0f;
            }
            __syncthreads();
            #pragma unroll
            for (int i = 0; i < 4; i++) {
                const int nn = nn_t + ty + i * 8;
                const int k = k_t + tx;
                dst[(size_t)nn * Cdim + k] = __float2half(sm[tx][ty + i * 8]);
            }
        }
    } else {
        // ---- prep_l2t: src [D_, C] -> dst [C, Dp] ----
        const int sid = bid - 30720;
        const int z = sid >> 9;
        const int r = sid & 511;
        const int by = r >> 6, bx = r & 63;
        const float* src = (z == 0) ? w2 : (z == 1) ? a2 : (z == 2) ? v2 : g2;
        __half* dst = (z == 0) ? g_w2p : (z == 1) ? g_a2p : (z == 2) ? g_v2p : g_g2p;
        const int D_ = (z == 0) ? 128 : (z == 1) ? 128 : (z == 2) ? 64 : 224;
        const int Dp = (z == 3) ? 256 : 128;
        const int d_t = by * 32;
        if (d_t < Dp) {
            const int nn_t = bx * 32;
            const int tx = tid & 31, ty = tid >> 5;
            #pragma unroll
            for (int i = 0; i < 4; i++) {
                const int d = d_t + ty + i * 8;
                const int nn = nn_t + tx;
                sm[ty + i * 8][tx] = (d < D_) ? src[(size_t)d * Cdim + nn] : 0.0f;
            }
            __syncthreads();
            #pragma unroll
            for (int i = 0; i < 4; i++) {
                const int nn = nn_t + ty + i * 8;
                const int d = d_t + tx;
                dst[(size_t)nn * Dp + d] = __float2half(sm[tx][ty + i * 8]);
            }
        }
    }
}

// ---------------- launch ----------------
extern "C" void kernel_launch(void* const* d_in, const int* in_sizes, int n_in,
                              void* d_out, int out_size)
{
    const float* x   = (const float*)d_in[0];
    const float* vf  = (const float*)d_in[1];
    const float* x_r = (const float*)d_in[2];
    const float* x_w = (const float*)d_in[3];
    const float* x_k = (const float*)d_in[4];
    const float* x_v = (const float*)d_in[5];
    const float* x_a = (const float*)d_in[6];
    const float* x_g = (const float*)d_in[7];
    const float* w0  = (const float*)d_in[8];
    const float* w1  = (const float*)d_in[9];
    const float* w2  = (const float*)d_in[10];
    const float* a0  = (const float*)d_in[11];
    const float* a1  = (const float*)d_in[12];
    const float* a2  = (const float*)d_in[13];
    const float* v0  = (const float*)d_in[14];
    const float* v1  = (const float*)d_in[15];
    const float* v2  = (const float*)d_in[16];
    const float* g1  = (const float*)d_in[17];
    const float* g2  = (const float*)d_in[18];
    const float* k_k = (const float*)d_in[19];
    const float* k_a = (const float*)d_in[20];
    const float* Wr  = (const float*)d_in[21];
    const float* Wk  = (const float*)d_in[22];
    const float* Wv  = (const float*)d_in[23];
    (void)in_sizes; (void)n_in; (void)out_size;

    float* out = (float*)d_out;
    float* out_r  = out + 0 * BTC;
    float* out_w  = out + 1 * BTC;
    float* out_k  = out + 2 * BTC;
    float* out_v  = out + 3 * BTC;
    float* out_a  = out + 4 * BTC;
    float* out_g  = out + 5 * BTC;
    float* out_kk = out + 6 * BTC;
    float* out_vf = out + 7 * BTC;

    // 1. merged prologue (mix + all weight preps) in one flat launch
    prologue<<<32768, 256>>>(x, vf, x_r, x_w, x_k, x_v, x_a, x_g, out_vf,
                             Wr, Wk, Wv, w1, a1, v1, g1, w2, a2, v2, g2);

    // 2. all K=2048 GEMMs in one flat launch (big-3 first, s1 in the tail wave)
    gemm_k2048<<<3392, 256>>>(out_r);

    // 3. LoRA stage 2 (merged, fused epilogues; z==1 also emits k_final + kk)
    gemm_s2<<<dim3(Cdim / 128, Mrows / 128, 4), 256>>>(
        out_w, out_a, out_v, out_g, out_k, out_kk, w0, a0, v0, vf, k_k, k_a);
}